// round 9
// baseline (speedup 1.0000x reference)
#include <cuda_runtime.h>
#include <cstdint>

#define BB     256
#define II     1024
#define PP     128
#define HH     128
#define LPROT  1024

// smem (floats):
//  [0, 2048)       ent: 1024 x float2 {gate, (il | ip<<16)}
//  [2048, 3072)    wlist: 16 warps x 256 bytes
//  [3072, 19456)   acc: 128 x 128 f32
static const int WL_OFF  = 2048;
static const int ACC_OFF = 3072;
static const int SMEM_F  = ACC_OFF + 128 * HH;   // 19456
static const int SMEM_B  = SMEM_F * 4;           // 77824 bytes

__global__ __launch_bounds__(512, 2)
void ile_kernel(const float* __restrict__ param_enc,
                const float* __restrict__ h_prot,
                const float* __restrict__ w1,
                const float* __restrict__ b1,
                const int*   __restrict__ idx_lig,
                const int*   __restrict__ idx_prot,
                const int*   __restrict__ protein_idx,
                const int*   __restrict__ lig_offsets,
                float*       __restrict__ out)
{
    extern __shared__ float sm[];
    float2*        ent   = reinterpret_cast<float2*>(sm);
    unsigned char* wlist = reinterpret_cast<unsigned char*>(sm + WL_OFF);
    float*         acc   = sm + ACC_OFF;

    const int b    = blockIdx.x;
    const int tid  = threadIdx.x;
    const int wid  = tid >> 5;      // 0..15
    const int lane = tid & 31;
    const int e8   = lane & 7;      // column-eighth   (streaming)
    const int rsub = lane >> 3;     // row-within-warp (streaming)

    const float* pe   = param_enc + (size_t)b * II * PP;

    // ---- init: zero acc + pack (il | ip<<16), all threads, coalesced ----
    {
        float4 z = make_float4(0.f, 0.f, 0.f, 0.f);
        float4* a4 = reinterpret_cast<float4*>(acc);
        #pragma unroll
        for (int k = 0; k < 8; k++)
            a4[tid + 512 * k] = z;

        const int* il_b = idx_lig  + b * II;
        const int* ip_b = idx_prot + b * II;
        #pragma unroll
        for (int k = 0; k < 2; k++) {
            const int row = tid + 512 * k;
            ent[row].y = __uint_as_float((unsigned)il_b[row]
                                       | ((unsigned)ip_b[row] << 16));
        }
    }

    const float bias = b1[0];
    float4 wreg[4];
    #pragma unroll
    for (int k = 0; k < 4; k++)
        wreg[k] = *reinterpret_cast<const float4*>(w1 + 4 * e8 + 32 * k);

    const int pb = protein_idx[b];
    const float* hp = h_prot + (size_t)pb * LPROT * HH + 4 * lane;
    unsigned char* wl = wlist + wid * 256;

    // streaming geometry: t = 0..15, row(t) = 64*t + 4*wid + rsub
    const float* pr0 = pe + (size_t)(4 * wid + rsub) * PP + 4 * e8;
    const int tstep = 64 * PP;

    // prefetch t=0
    float4 pf[4];
    #pragma unroll
    for (int k = 0; k < 4; k++)
        pf[k] = __ldcs(reinterpret_cast<const float4*>(pr0 + 32 * k));

    // =====================================================================
    // Fused loop: 4 blocks of 256 rows. Stream gates (4 t-iters), prefetch
    // next block's first t-iter, barrier, compact, then a ROLLING gather
    // pipeline (sustained ~4 loads in flight) into the smem accumulator.
    // =====================================================================
    #pragma unroll
    for (int blk = 0; blk < 4; blk++) {
        // ---- stream this block's gates ----
        #pragma unroll
        for (int tt = 0; tt < 4; tt++) {
            const int t = blk * 4 + tt;
            float4 v[4];
            if (tt == 0) {
                v[0] = pf[0]; v[1] = pf[1]; v[2] = pf[2]; v[3] = pf[3];
            } else {
                const float* pc = pr0 + (size_t)t * tstep;
                #pragma unroll
                for (int k = 0; k < 4; k++)
                    v[k] = __ldcs(reinterpret_cast<const float4*>(pc + 32 * k));
            }
            float p0 = v[0].x * wreg[0].x + v[0].y * wreg[0].y
                     + v[0].z * wreg[0].z + v[0].w * wreg[0].w;
            float p1 = v[1].x * wreg[1].x + v[1].y * wreg[1].y
                     + v[1].z * wreg[1].z + v[1].w * wreg[1].w;
            float p2 = v[2].x * wreg[2].x + v[2].y * wreg[2].y
                     + v[2].z * wreg[2].z + v[2].w * wreg[2].w;
            float p3 = v[3].x * wreg[3].x + v[3].y * wreg[3].y
                     + v[3].z * wreg[3].z + v[3].w * wreg[3].w;
            float s = (p0 + p1) + (p2 + p3);
            s += __shfl_xor_sync(0xffffffffu, s, 1);
            s += __shfl_xor_sync(0xffffffffu, s, 2);
            s += __shfl_xor_sync(0xffffffffu, s, 4);
            if (e8 == 0) {
                const int row = 64 * t + 4 * wid + rsub;
                ent[row].x = s + bias;
            }
        }

        // ---- prefetch next block's first t-iter (in flight through gather) ----
        if (blk < 3) {
            const float* pn = pr0 + (size_t)(blk * 4 + 4) * tstep;
            #pragma unroll
            for (int k = 0; k < 4; k++)
                pf[k] = __ldcs(reinterpret_cast<const float4*>(pn + 32 * k));
        }

        __syncthreads();    // block's gates visible (and init, for blk 0)

        // ---- compact this block's survivors for my il-group ----
        const int j0b = blk * 256;
        int cnt = 0;
        #pragma unroll
        for (int j0 = 0; j0 < 256; j0 += 32) {
            float2 e = ent[j0b + j0 + lane];
            unsigned ix = __float_as_uint(e.y);
            bool mine = (e.x > 0.f) && (((ix >> 3) & 0xfu) == (unsigned)wid);
            unsigned bal = __ballot_sync(0xffffffffu, mine);
            int pos = cnt + __popc(bal & ((1u << lane) - 1u));
            if (mine) wl[pos] = (unsigned char)(j0 + lane);
            cnt += __popc(bal);
        }

        // ---- gather + smem accumulate: rolling pipeline, MLP ~4 ----
        {
            float    gq[4];
            unsigned ilp = 0;          // 8-bit il-low-3 per slot
            float4   hq[4];
            // prologue: fill slots 0..3 with entries 0..3 (wl entries are
            // always in-range bytes -> addresses safe even when q >= cnt)
            #pragma unroll
            for (int q = 0; q < 4; q++) {
                const int jj = j0b + (int)wl[q];
                float2 e = ent[jj];
                unsigned ix = __float_as_uint(e.y);
                gq[q] = e.x;
                ilp |= (ix & 7u) << (8 * q);
                hq[q] = *reinterpret_cast<const float4*>(hp + (size_t)(ix >> 16) * HH);
            }
            for (int i = 0; i < cnt; i += 4) {
                #pragma unroll
                for (int k = 0; k < 4; k++) {
                    if (i + k < cnt) {
                        // consume slot k (entry i+k)
                        const float g = gq[k];
                        const int il = 8 * wid + (int)((ilp >> (8 * k)) & 7u);
                        float4* ap = reinterpret_cast<float4*>(acc + il * HH + 4 * lane);
                        float4 a = *ap;          // same row per warp: conflict-free
                        a.x += g * hq[k].x;  a.y += g * hq[k].y;
                        a.z += g * hq[k].z;  a.w += g * hq[k].w;
                        *ap = a;
                        // refill slot k with entry i+k+4 (keeps 3-4 in flight)
                        if (i + k + 4 < cnt) {
                            const int jj = j0b + (int)wl[i + k + 4];
                            float2 e = ent[jj];
                            unsigned ix = __float_as_uint(e.y);
                            gq[k] = e.x;
                            ilp = (ilp & ~(255u << (8 * k))) | ((ix & 7u) << (8 * k));
                            hq[k] = *reinterpret_cast<const float4*>(hp + (size_t)(ix >> 16) * HH);
                        }
                    }
                }
            }
        }
        // no trailing barrier: next block reads disjoint ent rows; acc rows
        // and wlist are warp-private.
    }

    __syncthreads();    // all accumulation done

    // ---- writeout: all 512 threads, coalesced float4 streaming stores ----
    {
        const int off = lig_offsets[b];
        float4*       o4 = reinterpret_cast<float4*>(out + (size_t)off * HH);
        const float4* a4 = reinterpret_cast<const float4*>(acc);
        #pragma unroll
        for (int k = 0; k < 8; k++)
            __stcs(&o4[tid + 512 * k], a4[tid + 512 * k]);
    }
}

extern "C" void kernel_launch(void* const* d_in, const int* in_sizes, int n_in,
                              void* d_out, int out_size)
{
    (void)in_sizes; (void)n_in; (void)out_size;

    cudaFuncSetAttribute(ile_kernel,
                         cudaFuncAttributeMaxDynamicSharedMemorySize, SMEM_B);

    ile_kernel<<<BB, 512, SMEM_B>>>(
        (const float*)d_in[0], (const float*)d_in[1],
        (const float*)d_in[2], (const float*)d_in[3],
        (const int*)d_in[4],   (const int*)d_in[5],
        (const int*)d_in[6],   (const int*)d_in[7],
        (float*)d_out);
}

// round 10
// speedup vs baseline: 1.1405x; 1.1405x over previous
#include <cuda_runtime.h>
#include <cstdint>

#define BB     256
#define II     1024
#define PP     128
#define HH     128
#define LPROT  1024

// smem (floats):
//  [0, 2048)       ent: 1024 x float2 {gate, (il | ip<<16)}
//  [2048, 3072)    wlist: 16 warps x 256 bytes
//  [3072, 19456)   acc: 128 x 128 f32
static const int WL_OFF  = 2048;
static const int ACC_OFF = 3072;
static const int SMEM_F  = ACC_OFF + 128 * HH;   // 19456
static const int SMEM_B  = SMEM_F * 4;           // 77824 bytes

__global__ __launch_bounds__(512, 2)
void ile_kernel(const float* __restrict__ param_enc,
                const float* __restrict__ h_prot,
                const float* __restrict__ w1,
                const float* __restrict__ b1,
                const int*   __restrict__ idx_lig,
                const int*   __restrict__ idx_prot,
                const int*   __restrict__ protein_idx,
                const int*   __restrict__ lig_offsets,
                float*       __restrict__ out)
{
    extern __shared__ float sm[];
    float2*        ent   = reinterpret_cast<float2*>(sm);
    unsigned char* wlist = reinterpret_cast<unsigned char*>(sm + WL_OFF);
    float*         acc   = sm + ACC_OFF;

    const int b    = blockIdx.x;
    const int tid  = threadIdx.x;
    const int wid  = tid >> 5;      // 0..15
    const int lane = tid & 31;
    const int e8   = lane & 7;      // column-eighth   (streaming)
    const int rsub = lane >> 3;     // row-within-warp (streaming)

    const float* pe   = param_enc + (size_t)b * II * PP;

    // ---- init: zero acc + pack (il | ip<<16), all threads, coalesced ----
    {
        float4 z = make_float4(0.f, 0.f, 0.f, 0.f);
        float4* a4 = reinterpret_cast<float4*>(acc);
        #pragma unroll
        for (int k = 0; k < 8; k++)
            a4[tid + 512 * k] = z;

        const int* il_b = idx_lig  + b * II;
        const int* ip_b = idx_prot + b * II;
        #pragma unroll
        for (int k = 0; k < 2; k++) {
            const int row = tid + 512 * k;
            ent[row].y = __uint_as_float((unsigned)il_b[row]
                                       | ((unsigned)ip_b[row] << 16));
        }
    }

    const float bias = b1[0];
    float4 wreg[4];
    #pragma unroll
    for (int k = 0; k < 4; k++)
        wreg[k] = *reinterpret_cast<const float4*>(w1 + 4 * e8 + 32 * k);

    const int pb = protein_idx[b];
    const float* hp = h_prot + (size_t)pb * LPROT * HH + 4 * lane;
    unsigned char* wl = wlist + wid * 256;

    // streaming geometry: t = 0..15, row(t) = 64*t + 4*wid + rsub
    const float* pr0 = pe + (size_t)(4 * wid + rsub) * PP + 4 * e8;
    const int tstep = 64 * PP;

    // prefetch t=0
    float4 pf[4];
    #pragma unroll
    for (int k = 0; k < 4; k++)
        pf[k] = __ldcs(reinterpret_cast<const float4*>(pr0 + 32 * k));

    // =====================================================================
    // Fused loop: 4 blocks of 256 rows. Stream gates (4 t-iters), prefetch
    // next block's first t-iter, barrier, compact, gather (batched MLP 4)
    // into the smem accumulator while prefetch loads are outstanding.
    // =====================================================================
    #pragma unroll
    for (int blk = 0; blk < 4; blk++) {
        // ---- stream this block's gates ----
        #pragma unroll
        for (int tt = 0; tt < 4; tt++) {
            const int t = blk * 4 + tt;
            float4 v[4];
            if (tt == 0) {
                v[0] = pf[0]; v[1] = pf[1]; v[2] = pf[2]; v[3] = pf[3];
            } else {
                const float* pc = pr0 + (size_t)t * tstep;
                #pragma unroll
                for (int k = 0; k < 4; k++)
                    v[k] = __ldcs(reinterpret_cast<const float4*>(pc + 32 * k));
            }
            float p0 = v[0].x * wreg[0].x + v[0].y * wreg[0].y
                     + v[0].z * wreg[0].z + v[0].w * wreg[0].w;
            float p1 = v[1].x * wreg[1].x + v[1].y * wreg[1].y
                     + v[1].z * wreg[1].z + v[1].w * wreg[1].w;
            float p2 = v[2].x * wreg[2].x + v[2].y * wreg[2].y
                     + v[2].z * wreg[2].z + v[2].w * wreg[2].w;
            float p3 = v[3].x * wreg[3].x + v[3].y * wreg[3].y
                     + v[3].z * wreg[3].z + v[3].w * wreg[3].w;
            float s = (p0 + p1) + (p2 + p3);
            s += __shfl_xor_sync(0xffffffffu, s, 1);
            s += __shfl_xor_sync(0xffffffffu, s, 2);
            s += __shfl_xor_sync(0xffffffffu, s, 4);
            if (e8 == 0) {
                const int row = 64 * t + 4 * wid + rsub;
                ent[row].x = s + bias;
            }
        }

        // ---- prefetch next block's first t-iter (in flight through gather) ----
        if (blk < 3) {
            const float* pn = pr0 + (size_t)(blk * 4 + 4) * tstep;
            #pragma unroll
            for (int k = 0; k < 4; k++)
                pf[k] = __ldcs(reinterpret_cast<const float4*>(pn + 32 * k));
        }

        __syncthreads();    // block's gates visible (and init, for blk 0)

        // ---- compact this block's survivors for my il-group ----
        const int j0b = blk * 256;
        int cnt = 0;
        #pragma unroll
        for (int j0 = 0; j0 < 256; j0 += 32) {
            float2 e = ent[j0b + j0 + lane];
            unsigned ix = __float_as_uint(e.y);
            bool mine = (e.x > 0.f) && (((ix & 0xffffu) >> 3) == (unsigned)wid);
            unsigned bal = __ballot_sync(0xffffffffu, mine);
            int pos = cnt + __popc(bal & ((1u << lane) - 1u));
            if (mine) wl[pos] = (unsigned char)(j0 + lane);
            cnt += __popc(bal);
        }

        // ---- gather + smem accumulate, batched, 4 loads in flight ----
        for (int i = 0; i < cnt; i += 4) {
            float    gq[4];
            unsigned ilp = 0;
            float4   hq[4];
            #pragma unroll
            for (int q = 0; q < 4; q++) {
                const bool v = (i + q) < cnt;
                const int jj = j0b + (int)wl[v ? (i + q) : i];
                float2 e = ent[jj];
                unsigned ix = __float_as_uint(e.y);
                gq[q] = v ? e.x : 0.f;
                ilp |= (ix & 7u) << (8 * q);
                hq[q] = *reinterpret_cast<const float4*>(hp + (size_t)(ix >> 16) * HH);
            }
            #pragma unroll
            for (int q = 0; q < 4; q++) {
                const float g = gq[q];
                const int il = 8 * wid + (int)((ilp >> (8 * q)) & 7u);
                float4* ap = reinterpret_cast<float4*>(acc + il * HH + 4 * lane);
                float4 a = *ap;                 // same row per warp: conflict-free
                a.x += g * hq[q].x;  a.y += g * hq[q].y;
                a.z += g * hq[q].z;  a.w += g * hq[q].w;
                *ap = a;
            }
        }
        // no trailing barrier: next block reads disjoint ent rows; acc rows
        // and wlist are warp-private.
    }

    // ---- per-warp writeout: NO final barrier. Warp wid owns acc rows
    //      [8*wid, 8*wid+8); lanes read back exactly the smem slices they
    //      themselves wrote (same-thread ordering). Early-finishing warps
    //      overlap their stores with laggards' gathers. ----
    {
        const int off = lig_offsets[b];
        const int rb  = 8 * wid;
        float* ob = out + (size_t)(off + rb) * HH + 4 * lane;
        const float* ab = acc + rb * HH + 4 * lane;
        #pragma unroll
        for (int r = 0; r < 8; r++)
            __stcs(reinterpret_cast<float4*>(ob + r * HH),
                   *reinterpret_cast<const float4*>(ab + r * HH));
    }
}

extern "C" void kernel_launch(void* const* d_in, const int* in_sizes, int n_in,
                              void* d_out, int out_size)
{
    (void)in_sizes; (void)n_in; (void)out_size;

    cudaFuncSetAttribute(ile_kernel,
                         cudaFuncAttributeMaxDynamicSharedMemorySize, SMEM_B);

    ile_kernel<<<BB, 512, SMEM_B>>>(
        (const float*)d_in[0], (const float*)d_in[1],
        (const float*)d_in[2], (const float*)d_in[3],
        (const int*)d_in[4],   (const int*)d_in[5],
        (const int*)d_in[6],   (const int*)d_in[7],
        (float*)d_out);
}